// round 1
// baseline (speedup 1.0000x reference)
#include <cuda_runtime.h>
#include <cuda_bf16.h>
#include <cstdint>

// Problem constants
#define BS_     4096
#define IN_DIM_ 2048
#define NN_     16384
#define DTOT_   129      // 2*K+1 + SLACK = 65 + 64
#define KPAD_   144      // padded K for the big GEMM (multiple of 16)
#define INV_SQRT_N_ 0.0078125f          // 1/128 exact
#define SQRT2_      1.41421356237309515f

// Scratch (allocation-free rule: __device__ globals)
__device__ float g_buf[BS_ * KPAD_];          // [4096][144] coefficients
__device__ float M_buf[KPAD_ * NN_];          // [144][16384] basis (ones/cos/sin/Ws^T, zero pad)

// ---------------------------------------------------------------------------
// Kernel 1: g = scale( x @ W_proj^T + b_proj ), zero-padded to KPAD_
// Tiles: BM1=64 (batch) x BN1=32 (d) x BK1=32, 256 threads, 4x2 micro-tile
// ---------------------------------------------------------------------------
#define BM1 64
#define BN1 32
#define BK1 32

__global__ __launch_bounds__(256) void proj_kernel(
    const float* __restrict__ x,
    const float* __restrict__ Wp,
    const float* __restrict__ bp)
{
    __shared__ float Xs[BK1][BM1 + 1];   // [k][b]
    __shared__ float Wsm[BK1][BN1 + 1];  // [k][d]

    const int tid = threadIdx.x;
    const int bm = blockIdx.y * BM1;
    const int bn = blockIdx.x * BN1;
    const int tx = tid & 15;     // d  (x2)
    const int ty = tid >> 4;     // b  (x4)

    float acc[4][2] = {};

    for (int kk = 0; kk < IN_DIM_; kk += BK1) {
        // load X tile: 64 rows x 32 k  (512 float4, 2 per thread)
        #pragma unroll
        for (int r = 0; r < 2; r++) {
            int id = tid + r * 256;
            int row = id >> 3;          // 0..63
            int c4  = id & 7;           // 0..7
            float4 v = *(const float4*)(x + (size_t)(bm + row) * IN_DIM_ + kk + c4 * 4);
            Xs[c4 * 4 + 0][row] = v.x;
            Xs[c4 * 4 + 1][row] = v.y;
            Xs[c4 * 4 + 2][row] = v.z;
            Xs[c4 * 4 + 3][row] = v.w;
        }
        // load W tile: 32 d-rows x 32 k (256 float4, 1 per thread), guard d<129
        {
            int row = tid >> 3;         // 0..31
            int c4  = tid & 7;
            int d   = bn + row;
            float4 v = make_float4(0.f, 0.f, 0.f, 0.f);
            if (d < DTOT_)
                v = *(const float4*)(Wp + (size_t)d * IN_DIM_ + kk + c4 * 4);
            Wsm[c4 * 4 + 0][row] = v.x;
            Wsm[c4 * 4 + 1][row] = v.y;
            Wsm[c4 * 4 + 2][row] = v.z;
            Wsm[c4 * 4 + 3][row] = v.w;
        }
        __syncthreads();

        #pragma unroll
        for (int k = 0; k < BK1; k++) {
            float b0 = Wsm[k][tx * 2 + 0];
            float b1 = Wsm[k][tx * 2 + 1];
            #pragma unroll
            for (int i = 0; i < 4; i++) {
                float a = Xs[k][ty * 4 + i];
                acc[i][0] += a * b0;
                acc[i][1] += a * b1;
            }
        }
        __syncthreads();
    }

    // Epilogue: add bias, fold 1/sqrt(N) and sqrt(2) scales, zero pad
    #pragma unroll
    for (int i = 0; i < 4; i++) {
        int b = bm + ty * 4 + i;
        #pragma unroll
        for (int j = 0; j < 2; j++) {
            int d = bn + tx * 2 + j;
            if (d < KPAD_) {
                float v = 0.f;
                if (d < DTOT_) {
                    v = acc[i][j] + bp[d];
                    if (d == 0)        v *= INV_SQRT_N_;
                    else if (d <= 64)  v *= INV_SQRT_N_ * SQRT2_;
                    // d in [65,128]: slack, scale 1
                }
                g_buf[(size_t)b * KPAD_ + d] = v;
            }
        }
    }
}

// ---------------------------------------------------------------------------
// Kernel 2: build M basis.
//   row 0        : 1
//   row 2k-1     : cos(2*pi*k*n/N)   k=1..32   (exact arg via (k*n)&(N-1))
//   row 2k       : sin(2*pi*k*n/N)
//   row 65+j     : Ws[n][j]          j=0..63   (transposed slack weights)
//   rows 129..143: 0
// ---------------------------------------------------------------------------
__global__ __launch_bounds__(256) void build_M_kernel(const float* __restrict__ Ws)
{
    const int n = blockIdx.x * 256 + threadIdx.x;
    M_buf[n] = 1.0f;
    #pragma unroll
    for (int k = 1; k <= 32; k++) {
        int m = (k * n) & (NN_ - 1);
        float t = (float)(2 * m) * (1.0f / (float)NN_);  // exact: 2m/16384
        float s, c;
        sincospif(t, &s, &c);                            // sin/cos(2*pi*m/N)
        M_buf[(size_t)(2 * k - 1) * NN_ + n] = c;
        M_buf[(size_t)(2 * k)     * NN_ + n] = s;
    }
    #pragma unroll 8
    for (int j = 0; j < 64; j++)
        M_buf[(size_t)(65 + j) * NN_ + n] = Ws[(size_t)n * 64 + j];
    #pragma unroll
    for (int r = DTOT_; r < KPAD_; r++)
        M_buf[(size_t)r * NN_ + n] = 0.f;
}

// ---------------------------------------------------------------------------
// Kernel 3: out[4096][16384] = g[4096][144] @ M[144][16384]
// Classic fp32 tiled GEMM: BM=64, BN=64, BK=16, 256 threads, 4x4 micro-tile
// ---------------------------------------------------------------------------
#define BM3 64
#define BN3 64
#define BK3 16
#define AROW_ 68   // padded As row length (16B-aligned, reduces store conflicts)

__global__ __launch_bounds__(256) void out_gemm_kernel(float* __restrict__ C)
{
    __shared__ float As[BK3][AROW_];   // [k][b]
    __shared__ float Bs[BK3][BN3];     // [k][n]

    const int tid = threadIdx.x;
    const int bm = blockIdx.y * BM3;
    const int bn = blockIdx.x * BN3;
    const int tx = tid & 15;     // n (x4)
    const int ty = tid >> 4;     // b (x4)

    float acc[4][4] = {};

    for (int kk = 0; kk < KPAD_; kk += BK3) {
        // A tile: 64 b-rows x 16 k = 256 float4, one per thread (transposed store)
        {
            int row = tid >> 2;         // 0..63
            int c4  = tid & 3;          // 0..3
            float4 v = *(const float4*)(&g_buf[(size_t)(bm + row) * KPAD_ + kk + c4 * 4]);
            As[c4 * 4 + 0][row] = v.x;
            As[c4 * 4 + 1][row] = v.y;
            As[c4 * 4 + 2][row] = v.z;
            As[c4 * 4 + 3][row] = v.w;
        }
        // B tile: 16 k-rows x 64 n = 256 float4, one per thread (direct store)
        {
            int k  = tid >> 4;          // 0..15
            int c4 = tid & 15;          // 0..15
            float4 v = *(const float4*)(&M_buf[(size_t)(kk + k) * NN_ + bn + c4 * 4]);
            *(float4*)(&Bs[k][c4 * 4]) = v;
        }
        __syncthreads();

        #pragma unroll
        for (int k = 0; k < BK3; k++) {
            float4 av = *(const float4*)(&As[k][ty * 4]);
            float4 bv = *(const float4*)(&Bs[k][tx * 4]);
            float a[4] = {av.x, av.y, av.z, av.w};
            float b[4] = {bv.x, bv.y, bv.z, bv.w};
            #pragma unroll
            for (int i = 0; i < 4; i++)
                #pragma unroll
                for (int j = 0; j < 4; j++)
                    acc[i][j] += a[i] * b[j];
        }
        __syncthreads();
    }

    #pragma unroll
    for (int i = 0; i < 4; i++) {
        float4 v = make_float4(acc[i][0], acc[i][1], acc[i][2], acc[i][3]);
        *(float4*)(&C[(size_t)(bm + ty * 4 + i) * NN_ + bn + tx * 4]) = v;
    }
}

// ---------------------------------------------------------------------------
extern "C" void kernel_launch(void* const* d_in, const int* in_sizes, int n_in,
                              void* d_out, int out_size)
{
    const float* x  = (const float*)d_in[0];   // [4096, 2048]
    const float* Wp = (const float*)d_in[1];   // [129, 2048]
    const float* bp = (const float*)d_in[2];   // [129]
    const float* Ws = (const float*)d_in[3];   // [16384, 64]
    float* out = (float*)d_out;                // [4096, 16384]

    // g = scaled projection  (d tiles: ceil(144/32)=5)
    proj_kernel<<<dim3(5, BS_ / BM1), 256>>>(x, Wp, bp);
    // M = [ones; cos/sin basis; Ws^T; zero pad]
    build_M_kernel<<<NN_ / 256, 256>>>(Ws);
    // out = g @ M
    out_gemm_kernel<<<dim3(NN_ / BN3, BS_ / BM3), 256>>>(out);
}